// round 3
// baseline (speedup 1.0000x reference)
#include <cuda_runtime.h>

#define N_SRCN 50000
#define N_DSTN 50000
#define N_E    1600000
#define DIN    128
#define KH     8
#define DOUTH  16
#define NEG_SLOPE 0.2f

// ---------------- scratch (static device globals; no allocation) ----------------
__device__ __align__(16) float g_hs[N_SRCN * 128];   // projected src features
__device__ __align__(16) float g_el[N_SRCN * KH];    // src attention logits
__device__ __align__(16) float g_er[N_DSTN * KH];    // dst attention logits
__device__ __align__(16) float g_v[DIN * KH];        // W_dst contracted with attn_r
__device__ float g_c[KH];                            // bias contribution to er
__device__ int   g_cnt[N_DSTN];
__device__ int   g_off[N_DSTN];
__device__ int   g_cur[N_DSTN];
__device__ int   g_bsum[256];
__device__ int   g_srcs[N_E];                        // src index sorted by dst (CSR payload)
__device__ int   g_is64;

__device__ __forceinline__ float lrelu(float x) { return x >= 0.f ? x : NEG_SLOPE * x; }
__device__ __forceinline__ int edge_at(const int* p, int e, int is64) { return is64 ? p[2 * e] : p[e]; }

__device__ __forceinline__ float sel8(float a0, float a1, float a2, float a3,
                                      float a4, float a5, float a6, float a7, int k) {
    float x0 = (k & 1) ? a1 : a0;
    float x1 = (k & 1) ? a3 : a2;
    float x2 = (k & 1) ? a5 : a4;
    float x3 = (k & 1) ? a7 : a6;
    float y0 = (k & 2) ? x1 : x0;
    float y1 = (k & 2) ? x3 : x2;
    return (k & 4) ? y1 : y0;
}

__device__ __forceinline__ float wmax(float v) {
    v = fmaxf(v, __shfl_xor_sync(0xffffffffu, v, 16));
    v = fmaxf(v, __shfl_xor_sync(0xffffffffu, v, 8));
    v = fmaxf(v, __shfl_xor_sync(0xffffffffu, v, 4));
    v = fmaxf(v, __shfl_xor_sync(0xffffffffu, v, 2));
    v = fmaxf(v, __shfl_xor_sync(0xffffffffu, v, 1));
    return v;
}
__device__ __forceinline__ float wsum(float v) {
    v += __shfl_xor_sync(0xffffffffu, v, 16);
    v += __shfl_xor_sync(0xffffffffu, v, 8);
    v += __shfl_xor_sync(0xffffffffu, v, 4);
    v += __shfl_xor_sync(0xffffffffu, v, 2);
    v += __shfl_xor_sync(0xffffffffu, v, 1);
    return v;
}

// ---------------- detect int64 vs int32 index layout ----------------
__global__ void detect_kernel(const int* s) {
    __shared__ int any;
    if (threadIdx.x == 0) any = 0;
    __syncthreads();
    if (s[2 * threadIdx.x + 1] != 0) any = 1;   // high word nonzero => int32 data
    __syncthreads();
    if (threadIdx.x == 0) g_is64 = any ? 0 : 1;
}

__global__ void zero_cnt_kernel() {
    int i = blockIdx.x * 256 + threadIdx.x;
    if (i < N_DSTN) g_cnt[i] = 0;
}

// ---------------- v = W_dst contracted with attn_r; c = bias part ----------------
__global__ void projv_kernel(const float* __restrict__ Wd, const float* __restrict__ bd,
                             const float* __restrict__ attn) {
    int d = threadIdx.x;  // 128 threads
    #pragma unroll
    for (int k = 0; k < KH; k++) {
        float s = 0.f;
        #pragma unroll
        for (int j = 0; j < DOUTH; j++)
            s += Wd[d * 128 + k * 16 + j] * attn[k * 32 + 16 + j];
        g_v[d * KH + k] = s;
    }
    if (d < KH) {
        float s = 0.f;
        #pragma unroll
        for (int j = 0; j < DOUTH; j++)
            s += bd[d * 16 + j] * attn[d * 32 + 16 + j];
        g_c[d] = s;
    }
}

// ---------------- hs = feat_src @ W_src + b_src  (fp32 tiled SGEMM) ----------------
#define GBM 64
#define GBK 16
__global__ void gemm_hs_kernel(const float* __restrict__ A, const float* __restrict__ W,
                               const float* __restrict__ bias) {
    __shared__ float As[GBK][68];      // stride 68: 16B-aligned f4 rows, mild STS conflict
    __shared__ float Ws[GBK][128];
    int tid = threadIdx.x;             // 256
    int tx = tid & 31;                 // col group (4 cols)
    int ty = tid >> 5;                 // row group (8 rows)
    int row0 = blockIdx.x * GBM;
    float acc[8][4];
    #pragma unroll
    for (int i = 0; i < 8; i++)
        #pragma unroll
        for (int c = 0; c < 4; c++) acc[i][c] = 0.f;

    for (int kk0 = 0; kk0 < DIN; kk0 += GBK) {
        {   // A tile: 64 rows x 16 cols, transposed into As[k][r]
            int r = tid >> 2;
            int c4 = (tid & 3) * 4;
            int gr = row0 + r;
            float4 v = (gr < N_SRCN) ? *(const float4*)(A + (size_t)gr * 128 + kk0 + c4)
                                     : make_float4(0.f, 0.f, 0.f, 0.f);
            As[c4 + 0][r] = v.x; As[c4 + 1][r] = v.y; As[c4 + 2][r] = v.z; As[c4 + 3][r] = v.w;
        }
        {   // W tile: 16 x 128
            int wr = tid >> 4;
            int wc = (tid & 15) * 8;
            float4 v0 = *(const float4*)(W + (size_t)(kk0 + wr) * 128 + wc);
            float4 v1 = *(const float4*)(W + (size_t)(kk0 + wr) * 128 + wc + 4);
            *(float4*)&Ws[wr][wc] = v0;
            *(float4*)&Ws[wr][wc + 4] = v1;
        }
        __syncthreads();
        #pragma unroll
        for (int kk = 0; kk < GBK; kk++) {
            float4 w = *(float4*)&Ws[kk][tx * 4];
            float4 a0 = *(float4*)&As[kk][ty * 8];
            float4 a1 = *(float4*)&As[kk][ty * 8 + 4];
            float ar[8] = {a0.x, a0.y, a0.z, a0.w, a1.x, a1.y, a1.z, a1.w};
            #pragma unroll
            for (int i = 0; i < 8; i++) {
                acc[i][0] += ar[i] * w.x; acc[i][1] += ar[i] * w.y;
                acc[i][2] += ar[i] * w.z; acc[i][3] += ar[i] * w.w;
            }
        }
        __syncthreads();
    }
    float4 b4 = *(const float4*)(bias + tx * 4);
    #pragma unroll
    for (int i = 0; i < 8; i++) {
        int gr = row0 + ty * 8 + i;
        if (gr < N_SRCN) {
            float4 o = make_float4(acc[i][0] + b4.x, acc[i][1] + b4.y,
                                   acc[i][2] + b4.z, acc[i][3] + b4.w);
            *(float4*)(g_hs + (size_t)gr * 128 + tx * 4) = o;
        }
    }
}

// ---------------- el[n,k] = sum_j hs[n,k,j] * attn_l[k,j] ----------------
__global__ void el_kernel(const float* __restrict__ attn) {
    int gw = (blockIdx.x * blockDim.x + threadIdx.x) >> 5;
    int lane = threadIdx.x & 31;
    if (gw >= N_SRCN) return;
    int k = lane >> 2, j0 = (lane & 3) * 4;
    float4 h = *(const float4*)(g_hs + (size_t)gw * 128 + lane * 4);
    float4 a = *(const float4*)(attn + k * 32 + j0);
    float v = h.x * a.x + h.y * a.y + h.z * a.z + h.w * a.w;
    v += __shfl_xor_sync(0xffffffffu, v, 1);
    v += __shfl_xor_sync(0xffffffffu, v, 2);
    if ((lane & 3) == 0) g_el[gw * KH + k] = v;
}

// ---------------- er[n,k] = feat_dst[n,:] @ v[:,k] + c[k] ----------------
__global__ void er_kernel(const float* __restrict__ feat) {
    __shared__ float vs[KH][DIN];   // transposed v for conflict-free f4 reads
    __shared__ float cs[KH];
    int t = threadIdx.x;
    for (int i = t; i < DIN * KH; i += 256) {
        int k = i >> 7, d = i & 127;
        vs[k][d] = g_v[d * KH + k];
    }
    if (t < KH) cs[t] = g_c[t];
    __syncthreads();
    int gw = (blockIdx.x * 256 + t) >> 5;
    int lane = t & 31;
    if (gw >= N_DSTN) return;
    float4 f = *(const float4*)(feat + (size_t)gw * 128 + lane * 4);
    int d0 = lane * 4;
    float p[8];
    #pragma unroll
    for (int k = 0; k < KH; k++) {
        float4 w = *(float4*)&vs[k][d0];
        p[k] = f.x * w.x + f.y * w.y + f.z * w.z + f.w * w.w;
    }
    #pragma unroll
    for (int k = 0; k < KH; k++) p[k] = wsum(p[k]);
    if (lane < KH) {
        float val = sel8(p[0], p[1], p[2], p[3], p[4], p[5], p[6], p[7], lane);
        g_er[gw * KH + lane] = val + cs[lane];
    }
}

// ---------------- CSR build ----------------
__global__ void hist_kernel(const int* __restrict__ dsti) {
    int e = blockIdx.x * 256 + threadIdx.x;
    int is64 = g_is64;
    int d = edge_at(dsti, e, is64);
    atomicAdd(&g_cnt[d], 1);
}

__global__ void scan_partial_kernel() {
    __shared__ int sm[256];
    int t = threadIdx.x, b = blockIdx.x;
    int i = b * 256 + t;
    int v = (i < N_DSTN) ? g_cnt[i] : 0;
    sm[t] = v;
    __syncthreads();
    for (int o = 1; o < 256; o <<= 1) {
        int add = (t >= o) ? sm[t - o] : 0;
        __syncthreads();
        sm[t] += add;
        __syncthreads();
    }
    if (i < N_DSTN) g_off[i] = sm[t] - v;
    if (t == 255) g_bsum[b] = sm[255];
}

__global__ void scan_bsum_kernel() {
    __shared__ int sm[256];
    int t = threadIdx.x;
    int v = (t < 196) ? g_bsum[t] : 0;
    sm[t] = v;
    __syncthreads();
    for (int o = 1; o < 256; o <<= 1) {
        int add = (t >= o) ? sm[t - o] : 0;
        __syncthreads();
        sm[t] += add;
        __syncthreads();
    }
    if (t < 196) g_bsum[t] = sm[t] - v;  // exclusive
}

__global__ void scan_add_kernel() {
    int t = threadIdx.x, b = blockIdx.x;
    int i = b * 256 + t;
    if (i < N_DSTN) {
        int o = g_off[i] + g_bsum[b];
        g_off[i] = o;
        g_cur[i] = o;
    }
}

__global__ void scatter_kernel(const int* __restrict__ srci, const int* __restrict__ dsti) {
    int e = blockIdx.x * 256 + threadIdx.x;
    int is64 = g_is64;
    int d = edge_at(dsti, e, is64);
    int s = edge_at(srci, e, is64);
    int pos = atomicAdd(&g_cur[d], 1);
    g_srcs[pos] = s;
}

// ---------------- fused edge-softmax + aggregation: one warp per dst node ----------------
__global__ void agg_kernel(float* __restrict__ out) {
    __shared__ float wsm[8][32][8];   // per-warp edge-chunk softmax weights
    int lane = threadIdx.x & 31;
    int wz = threadIdx.x >> 5;
    int n = blockIdx.x * 8 + wz;
    if (n >= N_DSTN) return;
    float4 acc = make_float4(0.f, 0.f, 0.f, 0.f);
    int cnt = g_cnt[n];
    int k = lane >> 2;
    const float NEGINF = __int_as_float(0xff800000);

    if (cnt > 0) {
        int base = g_off[n];
        float4 erl = *(const float4*)(g_er + n * KH);
        float4 erh = *(const float4*)(g_er + n * KH + 4);
        float m[8], s[8];
        #pragma unroll
        for (int j = 0; j < 8; j++) { m[j] = NEGINF; s[j] = 0.f; }
        float mk = NEGINF;

        for (int c0 = 0; c0 < cnt; c0 += 32) {
            int lim = min(32, cnt - c0);
            int sj = 0;
            float e[8];
            #pragma unroll
            for (int j = 0; j < 8; j++) e[j] = NEGINF;
            if (lane < lim) {
                sj = g_srcs[base + c0 + lane];
                float4 a = *(const float4*)(g_el + sj * KH);
                float4 b = *(const float4*)(g_el + sj * KH + 4);
                e[0] = lrelu(a.x + erl.x); e[1] = lrelu(a.y + erl.y);
                e[2] = lrelu(a.z + erl.z); e[3] = lrelu(a.w + erl.w);
                e[4] = lrelu(b.x + erh.x); e[5] = lrelu(b.y + erh.y);
                e[6] = lrelu(b.z + erh.z); e[7] = lrelu(b.w + erh.w);
            }
            float nm[8], p[8];
            #pragma unroll
            for (int j = 0; j < 8; j++) nm[j] = fmaxf(m[j], wmax(e[j]));
            #pragma unroll
            for (int j = 0; j < 8; j++) p[j] = __expf(e[j] - nm[j]);
            #pragma unroll
            for (int j = 0; j < 8; j++) s[j] = s[j] * __expf(m[j] - nm[j]) + wsum(p[j]);
            float nmk = sel8(nm[0], nm[1], nm[2], nm[3], nm[4], nm[5], nm[6], nm[7], k);
            float rs = __expf(mk - nmk);
            acc.x *= rs; acc.y *= rs; acc.z *= rs; acc.w *= rs;
            mk = nmk;
            #pragma unroll
            for (int j = 0; j < 8; j++) m[j] = nm[j];

            *(float4*)&wsm[wz][lane][0] = make_float4(p[0], p[1], p[2], p[3]);
            *(float4*)&wsm[wz][lane][4] = make_float4(p[4], p[5], p[6], p[7]);
            __syncwarp();
            #pragma unroll 4
            for (int j = 0; j < lim; j++) {
                int s_ = __shfl_sync(0xffffffffu, sj, j);
                float w = wsm[wz][j][k];
                float4 h = *(const float4*)(g_hs + (size_t)s_ * 128 + lane * 4);
                acc.x += w * h.x; acc.y += w * h.y;
                acc.z += w * h.z; acc.w += w * h.w;
            }
            __syncwarp();
        }
        float sk = sel8(s[0], s[1], s[2], s[3], s[4], s[5], s[6], s[7], k);
        float inv = 1.0f / sk;
        acc.x *= inv; acc.y *= inv; acc.z *= inv; acc.w *= inv;
    }
    *(float4*)(out + (size_t)n * 128 + lane * 4) = acc;
}

// ---------------- launch ----------------
extern "C" void kernel_launch(void* const* d_in, const int* in_sizes, int n_in,
                              void* d_out, int out_size) {
    const float* feat_src = (const float*)d_in[0];
    const float* feat_dst = (const float*)d_in[1];
    const float* W_src    = (const float*)d_in[2];
    const float* b_src    = (const float*)d_in[3];
    const float* W_dst    = (const float*)d_in[4];
    const float* b_dst    = (const float*)d_in[5];
    const float* attn     = (const float*)d_in[6];
    const int*   srci     = (const int*)d_in[7];
    const int*   dsti     = (const int*)d_in[8];
    float* out = (float*)d_out;

    detect_kernel<<<1, 256>>>(srci);
    zero_cnt_kernel<<<196, 256>>>();
    projv_kernel<<<1, 128>>>(W_dst, b_dst, attn);
    gemm_hs_kernel<<<(N_SRCN + GBM - 1) / GBM, 256>>>(feat_src, W_src, b_src);
    el_kernel<<<(N_SRCN + 7) / 8, 256>>>(attn);
    er_kernel<<<(N_DSTN + 7) / 8, 256>>>(feat_dst);
    hist_kernel<<<N_E / 256, 256>>>(dsti);
    scan_partial_kernel<<<196, 256>>>();
    scan_bsum_kernel<<<1, 256>>>();
    scan_add_kernel<<<196, 256>>>();
    scatter_kernel<<<N_E / 256, 256>>>(srci, dsti);
    agg_kernel<<<(N_DSTN + 7) / 8, 256>>>(out);
}

// round 6
// speedup vs baseline: 1.0904x; 1.0904x over previous
#include <cuda_runtime.h>

#define N_SRCN 50000
#define N_DSTN 50000
#define N_E    1600000
#define DIN    128
#define KH     8
#define DOUTH  16
#define NEG_SLOPE 0.2f

// ---------------- scratch (static device globals; no allocation) ----------------
__device__ __align__(16) float g_hs[N_SRCN * 128];   // projected src features
__device__ __align__(16) float g_ea[N_SRCN * 16];    // per-src {exp(el)[8], exp(0.2*el)[8]}
__device__ __align__(16) float g_eb[N_DSTN * 16];    // per-dst {exp(er)[8], exp(0.2*er)[8]}
__device__ __align__(16) float g_v[DIN * KH];        // W_dst contracted with attn_r
__device__ float g_c[KH];                            // bias contribution to er
__device__ int   g_cnt[N_DSTN];
__device__ int   g_off[N_DSTN];
__device__ int   g_cur[N_DSTN];
__device__ int   g_bsum[256];
__device__ int   g_srcs[N_E];                        // src index sorted by dst (CSR payload)
__device__ int   g_is64;

__device__ __forceinline__ int edge_at(const int* p, int e, int is64) { return is64 ? p[2 * e] : p[e]; }

__device__ __forceinline__ float sel8(float a0, float a1, float a2, float a3,
                                      float a4, float a5, float a6, float a7, int k) {
    float x0 = (k & 1) ? a1 : a0;
    float x1 = (k & 1) ? a3 : a2;
    float x2 = (k & 1) ? a5 : a4;
    float x3 = (k & 1) ? a7 : a6;
    float y0 = (k & 2) ? x1 : x0;
    float y1 = (k & 2) ? x3 : x2;
    return (k & 4) ? y1 : y0;
}

__device__ __forceinline__ float wsum(float v) {
    v += __shfl_xor_sync(0xffffffffu, v, 16);
    v += __shfl_xor_sync(0xffffffffu, v, 8);
    v += __shfl_xor_sync(0xffffffffu, v, 4);
    v += __shfl_xor_sync(0xffffffffu, v, 2);
    v += __shfl_xor_sync(0xffffffffu, v, 1);
    return v;
}

// ---------------- setup: detect idx width + zero counters + contract W_dst ----------------
__global__ void setup_kernel(const int* __restrict__ s, const float* __restrict__ Wd,
                             const float* __restrict__ bd, const float* __restrict__ attn) {
    int i = blockIdx.x * 256 + threadIdx.x;
    if (i < N_DSTN) g_cnt[i] = 0;
    if (blockIdx.x == 0) {
        __shared__ int any;
        int t = threadIdx.x;
        if (t == 0) any = 0;
        __syncthreads();
        if (s[2 * t + 1] != 0) any = 1;   // nonzero high word => int32 data
        __syncthreads();
        if (t == 0) g_is64 = any ? 0 : 1;
        if (t < 128) {
            int d = t;
            #pragma unroll
            for (int k = 0; k < KH; k++) {
                float acc = 0.f;
                #pragma unroll
                for (int j = 0; j < DOUTH; j++)
                    acc += Wd[d * 128 + k * 16 + j] * attn[k * 32 + 16 + j];
                g_v[d * KH + k] = acc;
            }
            if (d < KH) {
                float acc = 0.f;
                #pragma unroll
                for (int j = 0; j < DOUTH; j++)
                    acc += bd[d * 16 + j] * attn[d * 32 + 16 + j];
                g_c[d] = acc;
            }
        }
    }
}

// ---------------- hs = feat_src @ W_src + b_src, with fused el -> exp tables ----------------
#define GBM 64
#define GBK 16
__global__ void gemm_hs_kernel(const float* __restrict__ A, const float* __restrict__ W,
                               const float* __restrict__ bias, const float* __restrict__ attn) {
    __shared__ float As[GBK][68];
    __shared__ float Ws[GBK][128];
    int tid = threadIdx.x;             // 256
    int tx = tid & 31;                 // col group (4 cols)
    int ty = tid >> 5;                 // row group (8 rows)
    int row0 = blockIdx.x * GBM;
    float acc[8][4];
    #pragma unroll
    for (int i = 0; i < 8; i++)
        #pragma unroll
        for (int c = 0; c < 4; c++) acc[i][c] = 0.f;

    for (int kk0 = 0; kk0 < DIN; kk0 += GBK) {
        {   // A tile: 64 rows x 16 cols, transposed into As[k][r]
            int r = tid >> 2;
            int c4 = (tid & 3) * 4;
            int gr = row0 + r;
            float4 v = (gr < N_SRCN) ? *(const float4*)(A + (size_t)gr * 128 + kk0 + c4)
                                     : make_float4(0.f, 0.f, 0.f, 0.f);
            As[c4 + 0][r] = v.x; As[c4 + 1][r] = v.y; As[c4 + 2][r] = v.z; As[c4 + 3][r] = v.w;
        }
        {   // W tile: 16 x 128
            int wr = tid >> 4;
            int wc = (tid & 15) * 8;
            float4 v0 = *(const float4*)(W + (size_t)(kk0 + wr) * 128 + wc);
            float4 v1 = *(const float4*)(W + (size_t)(kk0 + wr) * 128 + wc + 4);
            *(float4*)&Ws[wr][wc] = v0;
            *(float4*)&Ws[wr][wc + 4] = v1;
        }
        __syncthreads();
        #pragma unroll
        for (int kk = 0; kk < GBK; kk++) {
            float4 w = *(float4*)&Ws[kk][tx * 4];
            float4 a0 = *(float4*)&As[kk][ty * 8];
            float4 a1 = *(float4*)&As[kk][ty * 8 + 4];
            float ar[8] = {a0.x, a0.y, a0.z, a0.w, a1.x, a1.y, a1.z, a1.w};
            #pragma unroll
            for (int i = 0; i < 8; i++) {
                acc[i][0] += ar[i] * w.x; acc[i][1] += ar[i] * w.y;
                acc[i][2] += ar[i] * w.z; acc[i][3] += ar[i] * w.w;
            }
        }
        __syncthreads();
    }
    float4 b4 = *(const float4*)(bias + tx * 4);
    int kh = tx >> 2;                  // head owned by this lane group of 4
    float4 ac = *(const float4*)(attn + kh * 32 + (tx & 3) * 4);  // attn_l coeffs for my 4 cols
    float elp[8];
    #pragma unroll
    for (int i = 0; i < 8; i++) {
        int gr = row0 + ty * 8 + i;
        float4 o = make_float4(acc[i][0] + b4.x, acc[i][1] + b4.y,
                               acc[i][2] + b4.z, acc[i][3] + b4.w);
        if (gr < N_SRCN)
            *(float4*)(g_hs + (size_t)gr * 128 + tx * 4) = o;
        elp[i] = o.x * ac.x + o.y * ac.y + o.z * ac.z + o.w * ac.w;
    }
    // reduce el over the 4 lanes of a head group, then write exp tables
    #pragma unroll
    for (int i = 0; i < 8; i++) {
        elp[i] += __shfl_xor_sync(0xffffffffu, elp[i], 1);
        elp[i] += __shfl_xor_sync(0xffffffffu, elp[i], 2);
    }
    int sub = tx & 3;
    if (sub < 2) {
        #pragma unroll
        for (int i = 0; i < 8; i++) {
            int gr = row0 + ty * 8 + i;
            if (gr < N_SRCN) {
                if (sub == 0) g_ea[(size_t)gr * 16 + kh] = __expf(elp[i]);
                else          g_ea[(size_t)gr * 16 + 8 + kh] = __expf(NEG_SLOPE * elp[i]);
            }
        }
    }
}

// ---------------- er[n,k] = feat_dst[n,:] @ v[:,k] + c[k] -> exp tables ----------------
__global__ void er_kernel(const float* __restrict__ feat) {
    __shared__ float vs[KH][DIN];
    __shared__ float cs[KH];
    int t = threadIdx.x;
    for (int i = t; i < DIN * KH; i += 256) {
        int k = i >> 7, d = i & 127;
        vs[k][d] = g_v[d * KH + k];
    }
    if (t < KH) cs[t] = g_c[t];
    __syncthreads();
    int gw = (blockIdx.x * 256 + t) >> 5;
    int lane = t & 31;
    if (gw >= N_DSTN) return;
    float4 f = *(const float4*)(feat + (size_t)gw * 128 + lane * 4);
    int d0 = lane * 4;
    float p[8];
    #pragma unroll
    for (int k = 0; k < KH; k++) {
        float4 w = *(float4*)&vs[k][d0];
        p[k] = f.x * w.x + f.y * w.y + f.z * w.z + f.w * w.w;
    }
    #pragma unroll
    for (int k = 0; k < KH; k++) p[k] = wsum(p[k]);
    if (lane < KH) {
        float er = sel8(p[0], p[1], p[2], p[3], p[4], p[5], p[6], p[7], lane) + cs[lane];
        g_eb[(size_t)gw * 16 + lane]     = __expf(er);
        g_eb[(size_t)gw * 16 + 8 + lane] = __expf(NEG_SLOPE * er);
    }
}

// ---------------- CSR build ----------------
__global__ void hist_kernel(const int* __restrict__ dsti) {
    int e = blockIdx.x * 256 + threadIdx.x;
    int is64 = g_is64;
    int d = edge_at(dsti, e, is64);
    atomicAdd(&g_cnt[d], 1);
}

__global__ void scan_partial_kernel() {
    __shared__ int sm[256];
    int t = threadIdx.x, b = blockIdx.x;
    int i = b * 256 + t;
    int v = (i < N_DSTN) ? g_cnt[i] : 0;
    sm[t] = v;
    __syncthreads();
    for (int o = 1; o < 256; o <<= 1) {
        int add = (t >= o) ? sm[t - o] : 0;
        __syncthreads();
        sm[t] += add;
        __syncthreads();
    }
    if (i < N_DSTN) g_off[i] = sm[t] - v;
    if (t == 255) g_bsum[b] = sm[255];
}

__global__ void scan_bsum_kernel() {
    __shared__ int sm[256];
    int t = threadIdx.x;
    int v = (t < 196) ? g_bsum[t] : 0;
    sm[t] = v;
    __syncthreads();
    for (int o = 1; o < 256; o <<= 1) {
        int add = (t >= o) ? sm[t - o] : 0;
        __syncthreads();
        sm[t] += add;
        __syncthreads();
    }
    if (t < 196) g_bsum[t] = sm[t] - v;  // exclusive
}

__global__ void scan_add_kernel() {
    int t = threadIdx.x, b = blockIdx.x;
    int i = b * 256 + t;
    if (i < N_DSTN) {
        int o = g_off[i] + g_bsum[b];
        g_off[i] = o;
        g_cur[i] = o;
    }
}

__global__ void scatter_kernel(const int* __restrict__ srci, const int* __restrict__ dsti) {
    int e = blockIdx.x * 256 + threadIdx.x;
    int is64 = g_is64;
    int d = edge_at(dsti, e, is64);
    int s = edge_at(srci, e, is64);
    int pos = atomicAdd(&g_cur[d], 1);
    g_srcs[pos] = s;
}

// ---------------- fused softmax + aggregation: one warp per dst, no exp, no max ----------------
__global__ void agg_kernel(float* __restrict__ out) {
    __shared__ float wsm[8][8][32];   // [warp][head][edge-in-chunk] — conflict-free
    int lane = threadIdx.x & 31;
    int wz = threadIdx.x >> 5;
    int n = blockIdx.x * 8 + wz;
    if (n >= N_DSTN) return;
    float4 acc = make_float4(0.f, 0.f, 0.f, 0.f);
    int cnt = g_cnt[n];
    int k = lane >> 2;

    if (cnt > 0) {
        int base = g_off[n];
        const float* eb = g_eb + (size_t)n * 16;
        float4 b1l = *(const float4*)(eb);
        float4 b1h = *(const float4*)(eb + 4);
        float4 b2l = *(const float4*)(eb + 8);
        float4 b2h = *(const float4*)(eb + 12);
        float s[8];
        #pragma unroll
        for (int j = 0; j < 8; j++) s[j] = 0.f;

        for (int c0 = 0; c0 < cnt; c0 += 32) {
            int lim = min(32, cnt - c0);
            int sj = 0;
            if (lane < lim) {
                sj = g_srcs[base + c0 + lane];
                const float* ea = g_ea + (size_t)sj * 16;
                float4 a1l = *(const float4*)(ea);
                float4 a1h = *(const float4*)(ea + 4);
                float4 a2l = *(const float4*)(ea + 8);
                float4 a2h = *(const float4*)(ea + 12);
                float p[8];
                // w = exp(el+er) if el+er>=0 else exp(0.2(el+er)); sign test: A1*B1>=1
                p[0] = a1l.x * b1l.x; p[0] = (p[0] >= 1.f) ? p[0] : a2l.x * b2l.x;
                p[1] = a1l.y * b1l.y; p[1] = (p[1] >= 1.f) ? p[1] : a2l.y * b2l.y;
                p[2] = a1l.z * b1l.z; p[2] = (p[2] >= 1.f) ? p[2] : a2l.z * b2l.z;
                p[3] = a1l.w * b1l.w; p[3] = (p[3] >= 1.f) ? p[3] : a2l.w * b2l.w;
                p[4] = a1h.x * b1h.x; p[4] = (p[4] >= 1.f) ? p[4] : a2h.x * b2h.x;
                p[5] = a1h.y * b1h.y; p[5] = (p[5] >= 1.f) ? p[5] : a2h.y * b2h.y;
                p[6] = a1h.z * b1h.z; p[6] = (p[6] >= 1.f) ? p[6] : a2h.z * b2h.z;
                p[7] = a1h.w * b1h.w; p[7] = (p[7] >= 1.f) ? p[7] : a2h.w * b2h.w;
                #pragma unroll
                for (int j = 0; j < 8; j++) {
                    s[j] += p[j];
                    wsm[wz][j][lane] = p[j];
                }
            }
            __syncwarp();
            #pragma unroll 4
            for (int j = 0; j < lim; j++) {
                int s_ = __shfl_sync(0xffffffffu, sj, j);
                float w = wsm[wz][k][j];
                float4 h = *(const float4*)(g_hs + (size_t)s_ * 128 + lane * 4);
                acc.x += w * h.x; acc.y += w * h.y;
                acc.z += w * h.z; acc.w += w * h.w;
            }
            __syncwarp();
        }
        #pragma unroll
        for (int j = 0; j < 8; j++) s[j] = wsum(s[j]);
        float sk = sel8(s[0], s[1], s[2], s[3], s[4], s[5], s[6], s[7], k);
        float inv = 1.0f / sk;
        acc.x *= inv; acc.y *= inv; acc.z *= inv; acc.w *= inv;
    }
    *(float4*)(out + (size_t)n * 128 + lane * 4) = acc;
}

// ---------------- launch ----------------
extern "C" void kernel_launch(void* const* d_in, const int* in_sizes, int n_in,
                              void* d_out, int out_size) {
    const float* feat_src = (const float*)d_in[0];
    const float* feat_dst = (const float*)d_in[1];
    const float* W_src    = (const float*)d_in[2];
    const float* b_src    = (const float*)d_in[3];
    const float* W_dst    = (const float*)d_in[4];
    const float* b_dst    = (const float*)d_in[5];
    const float* attn     = (const float*)d_in[6];
    const int*   srci     = (const int*)d_in[7];
    const int*   dsti     = (const int*)d_in[8];
    float* out = (float*)d_out;

    setup_kernel<<<196, 256>>>(srci, W_dst, b_dst, attn);
    gemm_hs_kernel<<<(N_SRCN + GBM - 1) / GBM, 256>>>(feat_src, W_src, b_src, attn);
    er_kernel<<<(N_DSTN + 7) / 8, 256>>>(feat_dst);
    hist_kernel<<<N_E / 256, 256>>>(dsti);
    scan_partial_kernel<<<196, 256>>>();
    scan_bsum_kernel<<<1, 256>>>();
    scan_add_kernel<<<196, 256>>>();
    scatter_kernel<<<N_E / 256, 256>>>(srci, dsti);
    agg_kernel<<<(N_DSTN + 7) / 8, 256>>>(out);
}

// round 11
// speedup vs baseline: 1.2763x; 1.1705x over previous
#include <cuda_runtime.h>
#include <cuda_fp16.h>

#define N_SRCN 50000
#define N_DSTN 50000
#define N_E    1600000
#define DIN    128
#define KH     8
#define DOUTH  16
#define NEG_SLOPE 0.2f

// ---------------- scratch (static device globals; no allocation) ----------------
__device__ __align__(16) __half g_hsh[N_SRCN * 128]; // projected src features (fp16)
__device__ __align__(16) float g_ea[N_SRCN * 16];    // per-src {exp(el)[8], exp(0.2*el)[8]}
__device__ __align__(16) float g_eb[N_DSTN * 16];    // per-dst {exp(er)[8], exp(0.2*er)[8]}
__device__ __align__(16) float g_v[DIN * KH];        // W_dst contracted with attn_r
__device__ float g_c[KH];                            // bias contribution to er
__device__ int   g_cnt[N_DSTN];
__device__ int   g_off[N_DSTN];
__device__ int   g_cur[N_DSTN];
__device__ int   g_bsum[256];
__device__ int   g_srcs[N_E];                        // src index sorted by dst (CSR payload)
__device__ int   g_is64;

__device__ __forceinline__ int edge_at(const int* p, int e, int is64) {
    if (is64) { int2 v = ((const int2*)p)[e]; return v.x; }
    return p[e];
}

__device__ __forceinline__ float sel8(float a0, float a1, float a2, float a3,
                                      float a4, float a5, float a6, float a7, int k) {
    float x0 = (k & 1) ? a1 : a0;
    float x1 = (k & 1) ? a3 : a2;
    float x2 = (k & 1) ? a5 : a4;
    float x3 = (k & 1) ? a7 : a6;
    float y0 = (k & 2) ? x1 : x0;
    float y1 = (k & 2) ? x3 : x2;
    return (k & 4) ? y1 : y0;
}

__device__ __forceinline__ float wsum(float v) {
    v += __shfl_xor_sync(0xffffffffu, v, 16);
    v += __shfl_xor_sync(0xffffffffu, v, 8);
    v += __shfl_xor_sync(0xffffffffu, v, 4);
    v += __shfl_xor_sync(0xffffffffu, v, 2);
    v += __shfl_xor_sync(0xffffffffu, v, 1);
    return v;
}

// ---------------- setup: detect idx width + zero counters + contract W_dst ----------------
__global__ void setup_kernel(const int* __restrict__ s, const float* __restrict__ Wd,
                             const float* __restrict__ bd, const float* __restrict__ attn) {
    int i = blockIdx.x * 256 + threadIdx.x;
    if (i < N_DSTN) g_cnt[i] = 0;
    if (blockIdx.x == 0) {
        __shared__ int any;
        int t = threadIdx.x;
        if (t == 0) any = 0;
        __syncthreads();
        if (s[2 * t + 1] != 0) any = 1;   // nonzero high word => int32 data
        __syncthreads();
        if (t == 0) g_is64 = any ? 0 : 1;
        if (t < 128) {
            int d = t;
            #pragma unroll
            for (int k = 0; k < KH; k++) {
                float acc = 0.f;
                #pragma unroll
                for (int j = 0; j < DOUTH; j++)
                    acc += Wd[d * 128 + k * 16 + j] * attn[k * 32 + 16 + j];
                g_v[d * KH + k] = acc;
            }
            if (d < KH) {
                float acc = 0.f;
                #pragma unroll
                for (int j = 0; j < DOUTH; j++)
                    acc += bd[d * 16 + j] * attn[d * 32 + 16 + j];
                g_c[d] = acc;
            }
        }
    }
}

// ---------------- hs = feat_src @ W_src + b_src, fused el->exp tables, fp16 store ----------------
#define GBM 64
#define GBK 16
__global__ void gemm_hs_kernel(const float* __restrict__ A, const float* __restrict__ W,
                               const float* __restrict__ bias, const float* __restrict__ attn) {
    __shared__ float As[GBK][68];
    __shared__ float Ws[GBK][128];
    int tid = threadIdx.x;             // 256
    int tx = tid & 31;                 // col group (4 cols)
    int ty = tid >> 5;                 // row group (8 rows)
    int row0 = blockIdx.x * GBM;
    float acc[8][4];
    #pragma unroll
    for (int i = 0; i < 8; i++)
        #pragma unroll
        for (int c = 0; c < 4; c++) acc[i][c] = 0.f;

    for (int kk0 = 0; kk0 < DIN; kk0 += GBK) {
        {   // A tile: 64 rows x 16 cols, transposed into As[k][r]
            int r = tid >> 2;
            int c4 = (tid & 3) * 4;
            int gr = row0 + r;
            float4 v = (gr < N_SRCN) ? *(const float4*)(A + (size_t)gr * 128 + kk0 + c4)
                                     : make_float4(0.f, 0.f, 0.f, 0.f);
            As[c4 + 0][r] = v.x; As[c4 + 1][r] = v.y; As[c4 + 2][r] = v.z; As[c4 + 3][r] = v.w;
        }
        {   // W tile: 16 x 128
            int wr = tid >> 4;
            int wc = (tid & 15) * 8;
            float4 v0 = *(const float4*)(W + (size_t)(kk0 + wr) * 128 + wc);
            float4 v1 = *(const float4*)(W + (size_t)(kk0 + wr) * 128 + wc + 4);
            *(float4*)&Ws[wr][wc] = v0;
            *(float4*)&Ws[wr][wc + 4] = v1;
        }
        __syncthreads();
        #pragma unroll
        for (int kk = 0; kk < GBK; kk++) {
            float4 w = *(float4*)&Ws[kk][tx * 4];
            float4 a0 = *(float4*)&As[kk][ty * 8];
            float4 a1 = *(float4*)&As[kk][ty * 8 + 4];
            float ar[8] = {a0.x, a0.y, a0.z, a0.w, a1.x, a1.y, a1.z, a1.w};
            #pragma unroll
            for (int i = 0; i < 8; i++) {
                acc[i][0] += ar[i] * w.x; acc[i][1] += ar[i] * w.y;
                acc[i][2] += ar[i] * w.z; acc[i][3] += ar[i] * w.w;
            }
        }
        __syncthreads();
    }
    float4 b4 = *(const float4*)(bias + tx * 4);
    int kh = tx >> 2;                  // head owned by this lane group of 4
    float4 ac = *(const float4*)(attn + kh * 32 + (tx & 3) * 4);  // attn_l coeffs for my 4 cols
    float elp[8];
    #pragma unroll
    for (int i = 0; i < 8; i++) {
        int gr = row0 + ty * 8 + i;
        float4 o = make_float4(acc[i][0] + b4.x, acc[i][1] + b4.y,
                               acc[i][2] + b4.z, acc[i][3] + b4.w);
        if (gr < N_SRCN) {
            __half2 h0 = __floats2half2_rn(o.x, o.y);
            __half2 h1 = __floats2half2_rn(o.z, o.w);
            uint2 pk;
            pk.x = *(unsigned*)&h0;
            pk.y = *(unsigned*)&h1;
            *(uint2*)(g_hsh + (size_t)gr * 128 + tx * 4) = pk;
        }
        elp[i] = o.x * ac.x + o.y * ac.y + o.z * ac.z + o.w * ac.w;
    }
    // reduce el over the 4 lanes of a head group, then write exp tables
    #pragma unroll
    for (int i = 0; i < 8; i++) {
        elp[i] += __shfl_xor_sync(0xffffffffu, elp[i], 1);
        elp[i] += __shfl_xor_sync(0xffffffffu, elp[i], 2);
    }
    int sub = tx & 3;
    if (sub < 2) {
        #pragma unroll
        for (int i = 0; i < 8; i++) {
            int gr = row0 + ty * 8 + i;
            if (gr < N_SRCN) {
                if (sub == 0) g_ea[(size_t)gr * 16 + kh] = __expf(elp[i]);
                else          g_ea[(size_t)gr * 16 + 8 + kh] = __expf(NEG_SLOPE * elp[i]);
            }
        }
    }
}

// ---------------- er[n,k] = feat_dst[n,:] @ v[:,k] + c[k] -> exp tables ----------------
__global__ void er_kernel(const float* __restrict__ feat) {
    __shared__ float vs[KH][DIN];
    __shared__ float cs[KH];
    int t = threadIdx.x;
    for (int i = t; i < DIN * KH; i += 256) {
        int k = i >> 7, d = i & 127;
        vs[k][d] = g_v[d * KH + k];
    }
    if (t < KH) cs[t] = g_c[t];
    __syncthreads();
    int gw = (blockIdx.x * 256 + t) >> 5;
    int lane = t & 31;
    if (gw >= N_DSTN) return;
    float4 f = *(const float4*)(feat + (size_t)gw * 128 + lane * 4);
    int d0 = lane * 4;
    float p[8];
    #pragma unroll
    for (int k = 0; k < KH; k++) {
        float4 w = *(float4*)&vs[k][d0];
        p[k] = f.x * w.x + f.y * w.y + f.z * w.z + f.w * w.w;
    }
    #pragma unroll
    for (int k = 0; k < KH; k++) p[k] = wsum(p[k]);
    if (lane < KH) {
        float er = sel8(p[0], p[1], p[2], p[3], p[4], p[5], p[6], p[7], lane) + cs[lane];
        g_eb[(size_t)gw * 16 + lane]     = __expf(er);
        g_eb[(size_t)gw * 16 + 8 + lane] = __expf(NEG_SLOPE * er);
    }
}

// ---------------- CSR build ----------------
__global__ void hist_kernel(const int* __restrict__ dsti) {
    int e = blockIdx.x * 256 + threadIdx.x;
    int is64 = g_is64;
    int d = edge_at(dsti, e, is64);
    atomicAdd(&g_cnt[d], 1);
}

__global__ void scan_partial_kernel() {
    __shared__ int sm[256];
    int t = threadIdx.x, b = blockIdx.x;
    int i = b * 256 + t;
    int v = (i < N_DSTN) ? g_cnt[i] : 0;
    sm[t] = v;
    __syncthreads();
    for (int o = 1; o < 256; o <<= 1) {
        int add = (t >= o) ? sm[t - o] : 0;
        __syncthreads();
        sm[t] += add;
        __syncthreads();
    }
    if (i < N_DSTN) g_off[i] = sm[t] - v;
    if (t == 255) g_bsum[b] = sm[255];
}

__global__ void scan_bsum_kernel() {
    __shared__ int sm[256];
    int t = threadIdx.x;
    int v = (t < 196) ? g_bsum[t] : 0;
    sm[t] = v;
    __syncthreads();
    for (int o = 1; o < 256; o <<= 1) {
        int add = (t >= o) ? sm[t - o] : 0;
        __syncthreads();
        sm[t] += add;
        __syncthreads();
    }
    if (t < 196) g_bsum[t] = sm[t] - v;  // exclusive
}

__global__ void scan_add_kernel() {
    int t = threadIdx.x, b = blockIdx.x;
    int i = b * 256 + t;
    if (i < N_DSTN) {
        int o = g_off[i] + g_bsum[b];
        g_off[i] = o;
        g_cur[i] = o;
    }
}

__global__ void scatter_kernel(const int* __restrict__ srci, const int* __restrict__ dsti) {
    int e = blockIdx.x * 256 + threadIdx.x;
    int is64 = g_is64;
    int d = edge_at(dsti, e, is64);
    int s = edge_at(srci, e, is64);
    int pos = atomicAdd(&g_cur[d], 1);
    g_srcs[pos] = s;
}

// ---------------- fused softmax + aggregation: one warp per dst, fp16 gathers ----------------
__global__ void agg_kernel(float* __restrict__ out) {
    __shared__ float wsm[8][8][32];   // [warp][head][edge-in-chunk] — conflict-free
    int lane = threadIdx.x & 31;
    int wz = threadIdx.x >> 5;
    int n = blockIdx.x * 8 + wz;
    if (n >= N_DSTN) return;
    float4 acc = make_float4(0.f, 0.f, 0.f, 0.f);
    int cnt = g_cnt[n];
    int k = lane >> 2;

    if (cnt > 0) {
        int base = g_off[n];
        const float* eb = g_eb + (size_t)n * 16;
        float4 b1l = *(const float4*)(eb);
        float4 b1h = *(const float4*)(eb + 4);
        float4 b2l = *(const float4*)(eb + 8);
        float4 b2h = *(const float4*)(eb + 12);
        float s[8];
        #pragma unroll
        for (int j = 0; j < 8; j++) s[j] = 0.f;

        for (int c0 = 0; c0 < cnt; c0 += 32) {
            int lim = min(32, cnt - c0);
            int sj = 0;
            if (lane < lim) {
                sj = g_srcs[base + c0 + lane];
                const float* ea = g_ea + (size_t)sj * 16;
                float4 a1l = *(const float4*)(ea);
                float4 a1h = *(const float4*)(ea + 4);
                float4 a2l = *(const float4*)(ea + 8);
                float4 a2h = *(const float4*)(ea + 12);
                float p[8];
                // w = exp(el+er) if el+er>=0 else exp(0.2(el+er)); sign test: A1*B1>=1
                p[0] = a1l.x * b1l.x; p[0] = (p[0] >= 1.f) ? p[0] : a2l.x * b2l.x;
                p[1] = a1l.y * b1l.y; p[1] = (p[1] >= 1.f) ? p[1] : a2l.y * b2l.y;
                p[2] = a1l.z * b1l.z; p[2] = (p[2] >= 1.f) ? p[2] : a2l.z * b2l.z;
                p[3] = a1l.w * b1l.w; p[3] = (p[3] >= 1.f) ? p[3] : a2l.w * b2l.w;
                p[4] = a1h.x * b1h.x; p[4] = (p[4] >= 1.f) ? p[4] : a2h.x * b2h.x;
                p[5] = a1h.y * b1h.y; p[5] = (p[5] >= 1.f) ? p[5] : a2h.y * b2h.y;
                p[6] = a1h.z * b1h.z; p[6] = (p[6] >= 1.f) ? p[6] : a2h.z * b2h.z;
                p[7] = a1h.w * b1h.w; p[7] = (p[7] >= 1.f) ? p[7] : a2h.w * b2h.w;
                #pragma unroll
                for (int j = 0; j < 8; j++) {
                    s[j] += p[j];
                    wsm[wz][j][lane] = p[j];
                }
            }
            __syncwarp();
            #pragma unroll 4
            for (int j = 0; j < lim; j++) {
                int s_ = __shfl_sync(0xffffffffu, sj, j);
                float w = wsm[wz][k][j];
                uint2 hv = *(const uint2*)(g_hsh + (size_t)s_ * 128 + lane * 4);
                float2 f0 = __half22float2(*(__half2*)&hv.x);
                float2 f1 = __half22float2(*(__half2*)&hv.y);
                acc.x += w * f0.x; acc.y += w * f0.y;
                acc.z += w * f1.x; acc.w += w * f1.y;
            }
            __syncwarp();
        }
        #pragma unroll
        for (int j = 0; j < 8; j++) s[j] = wsum(s[j]);
        float sk = sel8(s[0], s[1], s[2], s[3], s[4], s[5], s[6], s[7], k);
        float inv = 1.0f / sk;
        acc.x *= inv; acc.y *= inv; acc.z *= inv; acc.w *= inv;
    }
    *(float4*)(out + (size_t)n * 128 + lane * 4) = acc;
}

// ---------------- launch: fork CSR build onto a side stream, join before agg ----------------
extern "C" void kernel_launch(void* const* d_in, const int* in_sizes, int n_in,
                              void* d_out, int out_size) {
    const float* feat_src = (const float*)d_in[0];
    const float* feat_dst = (const float*)d_in[1];
    const float* W_src    = (const float*)d_in[2];
    const float* b_src    = (const float*)d_in[3];
    const float* W_dst    = (const float*)d_in[4];
    const float* b_dst    = (const float*)d_in[5];
    const float* attn     = (const float*)d_in[6];
    const int*   srci     = (const int*)d_in[7];
    const int*   dsti     = (const int*)d_in[8];
    float* out = (float*)d_out;

    // handles created on the first (uncaptured correctness) call; reused under capture
    static cudaStream_t s2 = nullptr;
    static cudaEvent_t evFork = nullptr, evJoin = nullptr;
    if (s2 == nullptr) {
        cudaStreamCreateWithFlags(&s2, cudaStreamNonBlocking);
        cudaEventCreateWithFlags(&evFork, cudaEventDisableTiming);
        cudaEventCreateWithFlags(&evJoin, cudaEventDisableTiming);
    }

    setup_kernel<<<196, 256>>>(srci, W_dst, b_dst, attn);

    // fork: CSR build on s2 (depends on setup for g_is64 + zeroed g_cnt)
    cudaEventRecord(evFork, 0);
    cudaStreamWaitEvent(s2, evFork, 0);
    hist_kernel<<<N_E / 256, 256, 0, s2>>>(dsti);
    scan_partial_kernel<<<196, 256, 0, s2>>>();
    scan_bsum_kernel<<<1, 256, 0, s2>>>();
    scan_add_kernel<<<196, 256, 0, s2>>>();
    scatter_kernel<<<N_E / 256, 256, 0, s2>>>(srci, dsti);
    cudaEventRecord(evJoin, s2);

    // feature side on the main stream, overlapped with CSR build
    gemm_hs_kernel<<<(N_SRCN + GBM - 1) / GBM, 256>>>(feat_src, W_src, b_src, attn);
    er_kernel<<<(N_DSTN + 7) / 8, 256>>>(feat_dst);

    // join, then aggregate
    cudaStreamWaitEvent(0, evJoin, 0);
    agg_kernel<<<(N_DSTN + 7) / 8, 256>>>(out);
}